// round 1
// baseline (speedup 1.0000x reference)
#include <cuda_runtime.h>
#include <math.h>

// ---------------- problem constants ----------------
#define BATCH 2
#define HH 256
#define WW 256
#define CDIM 96
#define HEADS 2
#define CH 48
#define QKV 288
#define HID 255
#define H2 510
#define NPIX 131072            // BATCH*HH*WW
#define PB 65536               // HH*WW

// ---------------- device scratch (no allocations allowed) ----------------
__device__ float g_t0[(size_t)NPIX * QKV];   // qkv pre-dwconv
__device__ float g_t1[(size_t)NPIX * QKV];   // qkv post-dwconv
__device__ float g_t2[(size_t)NPIX * H2];    // ffn hidden pre-dwconv
__device__ float g_gt[(size_t)NPIX * HID];   // gated
__device__ float g_y [(size_t)NPIX * CDIM];  // LN out / attn o (reused)
__device__ float g_x2[(size_t)NPIX * CDIM];  // x after attention residual
__device__ float g_nrm[2 * BATCH * CDIM];    // sum-of-squares q (ch 0..95), k (96..191) per batch
__device__ float g_att[BATCH * HEADS * CH * CH];

// ---------------- small helpers ----------------
__device__ __forceinline__ float gelu_exact(float v) {
    return 0.5f * v * (1.0f + erff(v * 0.70710678118654752f));
}

// ---------------- init: zero accumulators ----------------
__global__ void init_kernel(float* nrm, float* attn) {
    int t = threadIdx.x;
    for (int i = t; i < 2 * BATCH * CDIM; i += blockDim.x) nrm[i] = 0.f;
    for (int i = t; i < BATCH * HEADS * CH * CH; i += blockDim.x) attn[i] = 0.f;
}

// ---------------- per-pixel LayerNorm (biased var), warp per pixel ----------------
__global__ void ln_kernel(const float* __restrict__ in, const float* __restrict__ gamma,
                          const float* __restrict__ beta, float* __restrict__ out) {
    int warp = blockIdx.x * (blockDim.x >> 5) + (threadIdx.x >> 5);
    int lane = threadIdx.x & 31;
    int nwarps = gridDim.x * (blockDim.x >> 5);
    float g0 = gamma[lane], g1 = gamma[lane + 32], g2 = gamma[lane + 64];
    float b0 = beta[lane],  b1 = beta[lane + 32],  b2 = beta[lane + 64];
    for (int p = warp; p < NPIX; p += nwarps) {
        const float* xp = in + (size_t)p * CDIM;
        float v0 = xp[lane], v1 = xp[lane + 32], v2 = xp[lane + 64];
        float s  = v0 + v1 + v2;
        float ss = v0 * v0 + v1 * v1 + v2 * v2;
        #pragma unroll
        for (int o = 16; o > 0; o >>= 1) {
            s  += __shfl_xor_sync(0xffffffffu, s,  o);
            ss += __shfl_xor_sync(0xffffffffu, ss, o);
        }
        float mu = s * (1.f / 96.f);
        float var = ss * (1.f / 96.f) - mu * mu;
        float rstd = rsqrtf(var + 1e-5f);
        float* yp = out + (size_t)p * CDIM;
        yp[lane]      = (v0 - mu) * rstd * g0 + b0;
        yp[lane + 32] = (v1 - mu) * rstd * g1 + b1;
        yp[lane + 64] = (v2 - mu) * rstd * g2 + b2;
    }
}

// ---------------- generic tiled fp32 GEMM: C[M,N] = A[M,K] * B[K,N] (+R) ----------------
// BM=64, BN=64, BK=16, 256 threads, 4x4 register tile per thread. M multiple of 64.
__global__ void gemm_kernel(const float* __restrict__ A, const float* __restrict__ Bw,
                            const float* __restrict__ R, float* __restrict__ C,
                            int M, int K, int N) {
    __shared__ float As[16][68];   // [k][m], padded, 16B-aligned rows
    __shared__ float Bs[16][64];   // [k][n]
    int tid = threadIdx.x;
    int m0 = blockIdx.y * 64;
    int n0 = blockIdx.x * 64;
    int tx = tid & 15, ty = tid >> 4;
    float acc[4][4];
    #pragma unroll
    for (int r = 0; r < 4; r++)
        #pragma unroll
        for (int c = 0; c < 4; c++) acc[r][c] = 0.f;

    int Kt = (K + 15) >> 4;
    for (int kb = 0; kb < Kt; kb++) {
        int k0 = kb << 4;
        #pragma unroll
        for (int l = 0; l < 4; l++) {
            int idx = tid + l * 256;
            int ak = idx & 15, am = idx >> 4;
            int k = k0 + ak;
            As[ak][am] = (k < K) ? A[(size_t)(m0 + am) * K + k] : 0.f;
        }
        #pragma unroll
        for (int l = 0; l < 4; l++) {
            int idx = tid + l * 256;
            int bk = idx >> 6, bn = idx & 63;
            int k = k0 + bk, n = n0 + bn;
            Bs[bk][bn] = (k < K && n < N) ? Bw[(size_t)k * N + n] : 0.f;
        }
        __syncthreads();
        #pragma unroll
        for (int kk = 0; kk < 16; kk++) {
            float4 a4 = *(const float4*)&As[kk][ty * 4];
            float4 b4 = *(const float4*)&Bs[kk][tx * 4];
            float av[4] = {a4.x, a4.y, a4.z, a4.w};
            float bv[4] = {b4.x, b4.y, b4.z, b4.w};
            #pragma unroll
            for (int r = 0; r < 4; r++)
                #pragma unroll
                for (int c = 0; c < 4; c++) acc[r][c] += av[r] * bv[c];
        }
        __syncthreads();
    }
    #pragma unroll
    for (int r = 0; r < 4; r++) {
        int m = m0 + ty * 4 + r;
        #pragma unroll
        for (int c = 0; c < 4; c++) {
            int n = n0 + tx * 4 + c;
            if (n < N) {
                size_t o = (size_t)m * N + n;
                float v = acc[r][c];
                if (R) v += R[o];
                C[o] = v;
            }
        }
    }
}

// ---------------- depthwise 3x3, C=288, float4 channels, 4-wide x strip ----------------
__global__ void dwconv288_kernel(const float* __restrict__ in, const float* __restrict__ kern,
                                 float* __restrict__ out) {
    const int C4 = QKV / 4; // 72
    int idx = blockIdx.x * blockDim.x + threadIdx.x;
    if (idx >= (NPIX / 4) * C4) return;
    int c4 = idx % C4;
    int strip = idx / C4;
    int xs = (strip & 63) * 4;
    int y  = (strip >> 6) & 255;
    int b  = strip >> 14;

    float4 acc[4];
    #pragma unroll
    for (int ox = 0; ox < 4; ox++) acc[ox] = make_float4(0.f, 0.f, 0.f, 0.f);

    #pragma unroll
    for (int dy = -1; dy <= 1; dy++) {
        int yy = y + dy;
        if (yy < 0 || yy > 255) continue;
        const float* rowp = in + ((size_t)((b << 8) + yy) << 8) * QKV;
        float4 v[6];
        #pragma unroll
        for (int j = 0; j < 6; j++) {
            int xx = xs - 1 + j;
            if (xx >= 0 && xx <= 255)
                v[j] = *(const float4*)(rowp + (size_t)xx * QKV + c4 * 4);
            else
                v[j] = make_float4(0.f, 0.f, 0.f, 0.f);
        }
        #pragma unroll
        for (int dx = 0; dx < 3; dx++) {
            float4 kv = *(const float4*)(kern + (size_t)((dy + 1) * 3 + dx) * QKV + c4 * 4);
            #pragma unroll
            for (int ox = 0; ox < 4; ox++) {
                acc[ox].x += v[ox + dx].x * kv.x;
                acc[ox].y += v[ox + dx].y * kv.y;
                acc[ox].z += v[ox + dx].z * kv.z;
                acc[ox].w += v[ox + dx].w * kv.w;
            }
        }
    }
    float* op = out + ((size_t)((b << 16) + (y << 8) + xs)) * QKV + c4 * 4;
    #pragma unroll
    for (int ox = 0; ox < 4; ox++) *(float4*)(op + (size_t)ox * QKV) = acc[ox];
}

// ---------------- q/k sum-of-squares over spatial ----------------
__global__ void norms_kernel(const float* __restrict__ t1, float* __restrict__ nrm) {
    int b = blockIdx.y;
    int c = threadIdx.x;             // 0..191 (q: 0..95, k: 96..191)
    int s0 = blockIdx.x * 1024;
    const float* base = t1 + ((size_t)(b << 16) + s0) * QKV + c;
    float acc = 0.f;
    for (int s = 0; s < 1024; s++) {
        float v = base[(size_t)s * QKV];
        acc += v * v;
    }
    atomicAdd(&nrm[b * 192 + c], acc);
}

// ---------------- raw q*k^T accumulation (K=65536 outer product) ----------------
__global__ void qkt_kernel(const float* __restrict__ t1, float* __restrict__ attn) {
    __shared__ float qs[16][48];
    __shared__ float ks[16][48];
    int bh = blockIdx.y;                 // b*2+hd
    int b = bh >> 1, hd = bh & 1;
    int s0 = blockIdx.x * 2048;
    int tid = threadIdx.x;
    int tx = tid & 15, ty = tid >> 4;
    float acc[3][3];
    #pragma unroll
    for (int r = 0; r < 3; r++)
        #pragma unroll
        for (int c = 0; c < 3; c++) acc[r][c] = 0.f;

    const float* qbase = t1 + ((size_t)(b << 16)) * QKV + hd * CH;
    const float* kbase = qbase + CDIM;
    for (int st = 0; st < 2048; st += 16) {
        #pragma unroll
        for (int l = 0; l < 3; l++) {
            int idx = tid + l * 256;     // 768 = 16*48
            int si = idx / 48, e = idx % 48;
            size_t off = (size_t)(s0 + st + si) * QKV + e;
            qs[si][e] = qbase[off];
            ks[si][e] = kbase[off];
        }
        __syncthreads();
        #pragma unroll
        for (int si = 0; si < 16; si++) {
            float qv[3], kv[3];
            #pragma unroll
            for (int r = 0; r < 3; r++) qv[r] = qs[si][ty * 3 + r];
            #pragma unroll
            for (int c = 0; c < 3; c++) kv[c] = ks[si][tx * 3 + c];
            #pragma unroll
            for (int r = 0; r < 3; r++)
                #pragma unroll
                for (int c = 0; c < 3; c++) acc[r][c] += qv[r] * kv[c];
        }
        __syncthreads();
    }
    float* ab = attn + (size_t)bh * CH * CH;
    #pragma unroll
    for (int r = 0; r < 3; r++)
        #pragma unroll
        for (int c = 0; c < 3; c++)
            atomicAdd(&ab[(ty * 3 + r) * CH + (tx * 3 + c)], acc[r][c]);
}

// ---------------- normalize + temperature + softmax over rows ----------------
__global__ void softmax_kernel(float* __restrict__ attn, const float* __restrict__ nrm,
                               const float* __restrict__ temp) {
    int bh = blockIdx.x;
    int b = bh >> 1, hd = bh & 1;
    int d = threadIdx.x;
    if (d >= CH) return;
    float t = temp[hd];
    float rq = rsqrtf(nrm[b * 192 + hd * CH + d]);
    float* row = attn + (size_t)bh * CH * CH + d * CH;
    float vals[CH];
    float mx = -1e30f;
    #pragma unroll
    for (int e = 0; e < CH; e++) {
        float rk = rsqrtf(nrm[b * 192 + CDIM + hd * CH + e]);
        float v = row[e] * rq * rk * t;
        vals[e] = v;
        mx = fmaxf(mx, v);
    }
    float s = 0.f;
    #pragma unroll
    for (int e = 0; e < CH; e++) { vals[e] = expf(vals[e] - mx); s += vals[e]; }
    float inv = 1.f / s;
    #pragma unroll
    for (int e = 0; e < CH; e++) row[e] = vals[e] * inv;
}

// ---------------- o = attn @ v (per pixel, 32-pixel tiles) ----------------
__global__ void attnapply_kernel(const float* __restrict__ t1, const float* __restrict__ attn,
                                 float* __restrict__ o) {
    __shared__ float at[HEADS * CH * CH];  // 4608
    __shared__ float vs[32][CDIM];
    int b = blockIdx.y;
    int p0 = blockIdx.x * 32;
    int tid = threadIdx.x;
    for (int i = tid; i < HEADS * CH * CH; i += 256) at[i] = attn[(size_t)b * HEADS * CH * CH + i];
    const float* vbase = t1 + ((size_t)((b << 16) + p0)) * QKV + 2 * CDIM;
    #pragma unroll
    for (int l = 0; l < 12; l++) {
        int idx = tid + l * 256;           // 3072 = 32*96
        int p = idx / CDIM, c = idx % CDIM;
        vs[p][c] = vbase[(size_t)p * QKV + c];
    }
    __syncthreads();
    float* obase = o + ((size_t)((b << 16) + p0)) * CDIM;
    #pragma unroll
    for (int l = 0; l < 12; l++) {
        int idx = tid + l * 256;
        int p = idx / CDIM, c = idx % CDIM;
        int hd = c / CH, cm = c % CH;
        const float* arow = &at[(hd * CH + cm) * CH];
        const float* vrow = &vs[p][hd * CH];
        float s = 0.f;
        #pragma unroll
        for (int e = 0; e < CH; e++) s += arow[e] * vrow[e];
        obase[(size_t)p * CDIM + c] = s;
    }
}

// ---------------- depthwise 3x3 on 510ch + GELU gate -> 255ch ----------------
__global__ void dwgate_kernel(const float* __restrict__ in, const float* __restrict__ kern,
                              float* __restrict__ out) {
    int idx = blockIdx.x * blockDim.x + threadIdx.x;
    if (idx >= (NPIX / 4) * HID) return;
    int c = idx % HID;
    int strip = idx / HID;
    int xs = (strip & 63) * 4;
    int y  = (strip >> 6) & 255;
    int b  = strip >> 14;

    float accA[4] = {0.f, 0.f, 0.f, 0.f};
    float accB[4] = {0.f, 0.f, 0.f, 0.f};

    #pragma unroll
    for (int dy = -1; dy <= 1; dy++) {
        int yy = y + dy;
        if (yy < 0 || yy > 255) continue;
        const float* rowp = in + ((size_t)((b << 8) + yy) << 8) * H2;
        float va[6], vb[6];
        #pragma unroll
        for (int j = 0; j < 6; j++) {
            int xx = xs - 1 + j;
            if (xx >= 0 && xx <= 255) {
                const float* pp = rowp + (size_t)xx * H2;
                va[j] = pp[c];
                vb[j] = pp[c + HID];
            } else {
                va[j] = 0.f; vb[j] = 0.f;
            }
        }
        #pragma unroll
        for (int dx = 0; dx < 3; dx++) {
            size_t koff = (size_t)((dy + 1) * 3 + dx) * H2;
            float ka = kern[koff + c];
            float kb = kern[koff + c + HID];
            #pragma unroll
            for (int ox = 0; ox < 4; ox++) {
                accA[ox] += va[ox + dx] * ka;
                accB[ox] += vb[ox + dx] * kb;
            }
        }
    }
    size_t pbase = (size_t)((b << 16) + (y << 8) + xs);
    #pragma unroll
    for (int ox = 0; ox < 4; ox++)
        out[(pbase + ox) * HID + c] = gelu_exact(accA[ox]) * accB[ox];
}

// ---------------- launcher ----------------
extern "C" void kernel_launch(void* const* d_in, const int* in_sizes, int n_in,
                              void* d_out, int out_size) {
    const float* x     = (const float*)d_in[0];
    const float* ln1g  = (const float*)d_in[1];
    const float* ln1b  = (const float*)d_in[2];
    const float* ln2g  = (const float*)d_in[3];
    const float* ln2b  = (const float*)d_in[4];
    const float* qkvw  = (const float*)d_in[5];
    const float* qkvdw = (const float*)d_in[6];
    const float* temp  = (const float*)d_in[7];
    const float* aow   = (const float*)d_in[8];
    const float* fiw   = (const float*)d_in[9];
    const float* fdw   = (const float*)d_in[10];
    const float* fow   = (const float*)d_in[11];
    float* out = (float*)d_out;

    float *t0, *t1, *t2, *gt, *y, *x2, *nrm, *att;
    cudaGetSymbolAddress((void**)&t0,  g_t0);
    cudaGetSymbolAddress((void**)&t1,  g_t1);
    cudaGetSymbolAddress((void**)&t2,  g_t2);
    cudaGetSymbolAddress((void**)&gt,  g_gt);
    cudaGetSymbolAddress((void**)&y,   g_y);
    cudaGetSymbolAddress((void**)&x2,  g_x2);
    cudaGetSymbolAddress((void**)&nrm, g_nrm);
    cudaGetSymbolAddress((void**)&att, g_att);

    // attention branch
    init_kernel<<<1, 256>>>(nrm, att);
    ln_kernel<<<2048, 256>>>(x, ln1g, ln1b, y);
    gemm_kernel<<<dim3(5, 2048), 256>>>(y, qkvw, nullptr, t0, NPIX, CDIM, QKV);
    dwconv288_kernel<<<9216, 256>>>(t0, qkvdw, t1);
    norms_kernel<<<dim3(64, 2), 192>>>(t1, nrm);
    qkt_kernel<<<dim3(32, 4), 256>>>(t1, att);
    softmax_kernel<<<4, 64>>>(att, nrm, temp);
    attnapply_kernel<<<dim3(2048, 2), 256>>>(t1, att, y);
    gemm_kernel<<<dim3(2, 2048), 256>>>(y, aow, x, x2, NPIX, CDIM, CDIM);

    // FFN branch
    ln_kernel<<<2048, 256>>>(x2, ln2g, ln2b, y);
    gemm_kernel<<<dim3(8, 2048), 256>>>(y, fiw, nullptr, t2, NPIX, CDIM, H2);
    dwgate_kernel<<<32640, 256>>>(t2, fdw, gt);
    gemm_kernel<<<dim3(2, 2048), 256>>>(gt, fow, x2, out, NPIX, HID, CDIM);
}

// round 2
// speedup vs baseline: 1.3017x; 1.3017x over previous
#include <cuda_runtime.h>
#include <math.h>
#include <stdint.h>

// ---------------- problem constants ----------------
#define BATCH 2
#define HH 256
#define WW 256
#define CDIM 96
#define HEADS 2
#define CH 48
#define QKV 288
#define HID 255
#define HIDP 256               // padded stride for gated buffer
#define H2 510
#define NPIX 131072            // BATCH*HH*WW

// ---------------- device scratch (no allocations allowed) ----------------
__device__ float g_t0[(size_t)NPIX * QKV];   // qkv pre-dwconv
__device__ float g_t1[(size_t)NPIX * QKV];   // qkv post-dwconv
__device__ float g_t2[(size_t)NPIX * H2];    // ffn hidden pre-dwconv
__device__ float g_gt[(size_t)NPIX * HIDP];  // gated (padded to 256)
__device__ float g_y [(size_t)NPIX * CDIM];  // LN out / attn o (reused)
__device__ float g_x2[(size_t)NPIX * CDIM];  // x after attention residual
__device__ float g_nrm[2 * BATCH * CDIM];
__device__ float g_att[BATCH * HEADS * CH * CH];

// ---------------- helpers ----------------
__device__ __forceinline__ float gelu_exact(float v) {
    return 0.5f * v * (1.0f + erff(v * 0.70710678118654752f));
}
__device__ __forceinline__ uint32_t f2tf32(float f) {
    uint32_t r; asm("cvt.rna.tf32.f32 %0, %1;" : "=r"(r) : "f"(f)); return r;
}
__device__ __forceinline__ void mma_tf32(float* c, const uint32_t* a, const uint32_t* b) {
    asm volatile("mma.sync.aligned.m16n8k8.row.col.f32.tf32.tf32.f32 "
        "{%0,%1,%2,%3}, {%4,%5,%6,%7}, {%8,%9}, {%0,%1,%2,%3};\n"
        : "+f"(c[0]), "+f"(c[1]), "+f"(c[2]), "+f"(c[3])
        : "r"(a[0]), "r"(a[1]), "r"(a[2]), "r"(a[3]), "r"(b[0]), "r"(b[1]));
}

// ---------------- init: zero accumulators ----------------
__global__ void init_kernel(float* nrm, float* attn) {
    int t = threadIdx.x;
    for (int i = t; i < 2 * BATCH * CDIM; i += blockDim.x) nrm[i] = 0.f;
    for (int i = t; i < BATCH * HEADS * CH * CH; i += blockDim.x) attn[i] = 0.f;
}

// ---------------- per-pixel LayerNorm, warp per pixel ----------------
__global__ void ln_kernel(const float* __restrict__ in, const float* __restrict__ gamma,
                          const float* __restrict__ beta, float* __restrict__ out) {
    int warp = blockIdx.x * (blockDim.x >> 5) + (threadIdx.x >> 5);
    int lane = threadIdx.x & 31;
    int nwarps = gridDim.x * (blockDim.x >> 5);
    float g0 = gamma[lane], g1 = gamma[lane + 32], g2 = gamma[lane + 64];
    float b0 = beta[lane],  b1 = beta[lane + 32],  b2 = beta[lane + 64];
    for (int p = warp; p < NPIX; p += nwarps) {
        const float* xp = in + (size_t)p * CDIM;
        float v0 = xp[lane], v1 = xp[lane + 32], v2 = xp[lane + 64];
        float s  = v0 + v1 + v2;
        float ss = v0 * v0 + v1 * v1 + v2 * v2;
        #pragma unroll
        for (int o = 16; o > 0; o >>= 1) {
            s  += __shfl_xor_sync(0xffffffffu, s,  o);
            ss += __shfl_xor_sync(0xffffffffu, ss, o);
        }
        float mu = s * (1.f / 96.f);
        float var = ss * (1.f / 96.f) - mu * mu;
        float rstd = rsqrtf(var + 1e-5f);
        float* yp = out + (size_t)p * CDIM;
        yp[lane]      = (v0 - mu) * rstd * g0 + b0;
        yp[lane + 32] = (v1 - mu) * rstd * g1 + b1;
        yp[lane + 64] = (v2 - mu) * rstd * g2 + b2;
    }
}

// ---------------- tf32 tensor-core GEMM: C[M,N] = A[M,Ka(pad)] * B[Kb,N] (+R) ----------------
// BM=128, BN=64, BK=32, 256 threads, 8 warps (4M x 2N), each warp 32x32 via m16n8k8.
// Ka: A row stride AND padded K (multiple of 32, zero-padded region OK).
// Kb: real K rows of B (B load guarded).
__global__ void gemm_tf32_kernel(const float* __restrict__ A, const float* __restrict__ Bw,
                                 const float* __restrict__ R, float* __restrict__ C,
                                 int Ka, int Kb, int N) {
    __shared__ uint32_t As[128][36];   // [m][k], pad 4 -> conflict-free frag loads
    __shared__ uint32_t Bs[32][68];    // [k][n], pad 4
    int tid = threadIdx.x;
    int m0 = blockIdx.y * 128;
    int n0 = blockIdx.x * 64;
    int lane = tid & 31, warp = tid >> 5;
    int g = lane >> 2, tg = lane & 3;
    int warpM = warp & 3, warpN = warp >> 2;
    int mbase = warpM * 32, nbase = warpN * 32;

    float acc[2][4][4];
    #pragma unroll
    for (int mt = 0; mt < 2; mt++)
        #pragma unroll
        for (int nt = 0; nt < 4; nt++)
            #pragma unroll
            for (int i = 0; i < 4; i++) acc[mt][nt][i] = 0.f;

    int Kt = Ka >> 5;
    for (int kb = 0; kb < Kt; kb++) {
        int k0 = kb << 5;
        // A tile: 128x32 = 1024 float4 loads
        #pragma unroll
        for (int l = 0; l < 4; l++) {
            int f4 = tid + l * 256;
            int row = f4 >> 3, kq = (f4 & 7) << 2;
            float4 v = *(const float4*)(A + (size_t)(m0 + row) * Ka + k0 + kq);
            uint4 u;
            u.x = f2tf32(v.x); u.y = f2tf32(v.y); u.z = f2tf32(v.z); u.w = f2tf32(v.w);
            *(uint4*)&As[row][kq] = u;
        }
        // B tile: 32x64 scalars, guarded (L2-resident weights)
        #pragma unroll
        for (int l = 0; l < 8; l++) {
            int idx = tid + l * 256;
            int bk = idx >> 6, bn = idx & 63;
            int kk = k0 + bk, nn = n0 + bn;
            float v = (kk < Kb && nn < N) ? Bw[(size_t)kk * N + nn] : 0.f;
            Bs[bk][bn] = f2tf32(v);
        }
        __syncthreads();
        #pragma unroll
        for (int ks = 0; ks < 4; ks++) {
            int k = ks << 3;
            uint32_t af[2][4], bf[4][2];
            #pragma unroll
            for (int mt = 0; mt < 2; mt++) {
                int r = mbase + mt * 16 + g;
                af[mt][0] = As[r][k + tg];
                af[mt][1] = As[r + 8][k + tg];
                af[mt][2] = As[r][k + tg + 4];
                af[mt][3] = As[r + 8][k + tg + 4];
            }
            #pragma unroll
            for (int nt = 0; nt < 4; nt++) {
                int cc = nbase + nt * 8 + g;
                bf[nt][0] = Bs[k + tg][cc];
                bf[nt][1] = Bs[k + tg + 4][cc];
            }
            #pragma unroll
            for (int mt = 0; mt < 2; mt++)
                #pragma unroll
                for (int nt = 0; nt < 4; nt++)
                    mma_tf32(acc[mt][nt], af[mt], bf[nt]);
        }
        __syncthreads();
    }
    // epilogue
    #pragma unroll
    for (int mt = 0; mt < 2; mt++) {
        #pragma unroll
        for (int nt = 0; nt < 4; nt++) {
            #pragma unroll
            for (int i = 0; i < 4; i++) {
                int row = mbase + mt * 16 + g + ((i >> 1) << 3);
                int col = nbase + nt * 8 + tg * 2 + (i & 1);
                int n = n0 + col;
                if (n < N) {
                    size_t o = (size_t)(m0 + row) * N + n;
                    float v = acc[mt][nt][i];
                    if (R) v += R[o];
                    C[o] = v;
                }
            }
        }
    }
}

// ---------------- depthwise 3x3, C=288, float4 channels, 4-wide x strip ----------------
__global__ void dwconv288_kernel(const float* __restrict__ in, const float* __restrict__ kern,
                                 float* __restrict__ out) {
    const int C4 = QKV / 4; // 72
    int idx = blockIdx.x * blockDim.x + threadIdx.x;
    if (idx >= (NPIX / 4) * C4) return;
    int c4 = idx % C4;
    int strip = idx / C4;
    int xs = (strip & 63) * 4;
    int y  = (strip >> 6) & 255;
    int b  = strip >> 14;

    float4 acc[4];
    #pragma unroll
    for (int ox = 0; ox < 4; ox++) acc[ox] = make_float4(0.f, 0.f, 0.f, 0.f);

    #pragma unroll
    for (int dy = -1; dy <= 1; dy++) {
        int yy = y + dy;
        if (yy < 0 || yy > 255) continue;
        const float* rowp = in + ((size_t)((b << 8) + yy) << 8) * QKV;
        float4 v[6];
        #pragma unroll
        for (int j = 0; j < 6; j++) {
            int xx = xs - 1 + j;
            if (xx >= 0 && xx <= 255)
                v[j] = *(const float4*)(rowp + (size_t)xx * QKV + c4 * 4);
            else
                v[j] = make_float4(0.f, 0.f, 0.f, 0.f);
        }
        #pragma unroll
        for (int dx = 0; dx < 3; dx++) {
            float4 kv = *(const float4*)(kern + (size_t)((dy + 1) * 3 + dx) * QKV + c4 * 4);
            #pragma unroll
            for (int ox = 0; ox < 4; ox++) {
                acc[ox].x += v[ox + dx].x * kv.x;
                acc[ox].y += v[ox + dx].y * kv.y;
                acc[ox].z += v[ox + dx].z * kv.z;
                acc[ox].w += v[ox + dx].w * kv.w;
            }
        }
    }
    float* op = out + ((size_t)((b << 16) + (y << 8) + xs)) * QKV + c4 * 4;
    #pragma unroll
    for (int ox = 0; ox < 4; ox++) *(float4*)(op + (size_t)ox * QKV) = acc[ox];
}

// ---------------- q/k sum-of-squares over spatial ----------------
__global__ void norms_kernel(const float* __restrict__ t1, float* __restrict__ nrm) {
    int b = blockIdx.y;
    int c = threadIdx.x;             // 0..191
    int s0 = blockIdx.x * 1024;
    const float* base = t1 + ((size_t)(b << 16) + s0) * QKV + c;
    float acc = 0.f;
    for (int s = 0; s < 1024; s++) {
        float v = base[(size_t)s * QKV];
        acc += v * v;
    }
    atomicAdd(&nrm[b * 192 + c], acc);
}

// ---------------- raw q*k^T accumulation ----------------
__global__ void qkt_kernel(const float* __restrict__ t1, float* __restrict__ attn) {
    __shared__ float qs[16][48];
    __shared__ float ks[16][48];
    int bh = blockIdx.y;
    int b = bh >> 1, hd = bh & 1;
    int s0 = blockIdx.x * 2048;
    int tid = threadIdx.x;
    int tx = tid & 15, ty = tid >> 4;
    float acc[3][3];
    #pragma unroll
    for (int r = 0; r < 3; r++)
        #pragma unroll
        for (int c = 0; c < 3; c++) acc[r][c] = 0.f;

    const float* qbase = t1 + ((size_t)(b << 16)) * QKV + hd * CH;
    const float* kbase = qbase + CDIM;
    for (int st = 0; st < 2048; st += 16) {
        #pragma unroll
        for (int l = 0; l < 3; l++) {
            int idx = tid + l * 256;
            int si = idx / 48, e = idx % 48;
            size_t off = (size_t)(s0 + st + si) * QKV + e;
            qs[si][e] = qbase[off];
            ks[si][e] = kbase[off];
        }
        __syncthreads();
        #pragma unroll
        for (int si = 0; si < 16; si++) {
            float qv[3], kv[3];
            #pragma unroll
            for (int r = 0; r < 3; r++) qv[r] = qs[si][ty * 3 + r];
            #pragma unroll
            for (int c = 0; c < 3; c++) kv[c] = ks[si][tx * 3 + c];
            #pragma unroll
            for (int r = 0; r < 3; r++)
                #pragma unroll
                for (int c = 0; c < 3; c++) acc[r][c] += qv[r] * kv[c];
        }
        __syncthreads();
    }
    float* ab = attn + (size_t)bh * CH * CH;
    #pragma unroll
    for (int r = 0; r < 3; r++)
        #pragma unroll
        for (int c = 0; c < 3; c++)
            atomicAdd(&ab[(ty * 3 + r) * CH + (tx * 3 + c)], acc[r][c]);
}

// ---------------- normalize + temperature + softmax ----------------
__global__ void softmax_kernel(float* __restrict__ attn, const float* __restrict__ nrm,
                               const float* __restrict__ temp) {
    int bh = blockIdx.x;
    int b = bh >> 1, hd = bh & 1;
    int d = threadIdx.x;
    if (d >= CH) return;
    float t = temp[hd];
    float rq = rsqrtf(nrm[b * 192 + hd * CH + d]);
    float* row = attn + (size_t)bh * CH * CH + d * CH;
    float vals[CH];
    float mx = -1e30f;
    #pragma unroll
    for (int e = 0; e < CH; e++) {
        float rk = rsqrtf(nrm[b * 192 + CDIM + hd * CH + e]);
        float v = row[e] * rq * rk * t;
        vals[e] = v;
        mx = fmaxf(mx, v);
    }
    float s = 0.f;
    #pragma unroll
    for (int e = 0; e < CH; e++) { vals[e] = expf(vals[e] - mx); s += vals[e]; }
    float inv = 1.f / s;
    #pragma unroll
    for (int e = 0; e < CH; e++) row[e] = vals[e] * inv;
}

// ---------------- o = attn @ v ----------------
__global__ void attnapply_kernel(const float* __restrict__ t1, const float* __restrict__ attn,
                                 float* __restrict__ o) {
    __shared__ float at[HEADS * CH * CH];
    __shared__ float vs[32][CDIM];
    int b = blockIdx.y;
    int p0 = blockIdx.x * 32;
    int tid = threadIdx.x;
    for (int i = tid; i < HEADS * CH * CH; i += 256) at[i] = attn[(size_t)b * HEADS * CH * CH + i];
    const float* vbase = t1 + ((size_t)((b << 16) + p0)) * QKV + 2 * CDIM;
    #pragma unroll
    for (int l = 0; l < 12; l++) {
        int idx = tid + l * 256;
        int p = idx / CDIM, c = idx % CDIM;
        vs[p][c] = vbase[(size_t)p * QKV + c];
    }
    __syncthreads();
    float* obase = o + ((size_t)((b << 16) + p0)) * CDIM;
    #pragma unroll
    for (int l = 0; l < 12; l++) {
        int idx = tid + l * 256;
        int p = idx / CDIM, c = idx % CDIM;
        int hd = c / CH, cm = c % CH;
        const float* arow = &at[(hd * CH + cm) * CH];
        const float* vrow = &vs[p][hd * CH];
        float s = 0.f;
        #pragma unroll
        for (int e = 0; e < CH; e++) s += arow[e] * vrow[e];
        obase[(size_t)p * CDIM + c] = s;
    }
}

// ---------------- depthwise 3x3 on 510ch + GELU gate -> 255ch (stride-256 out) ----------------
__global__ void dwgate_kernel(const float* __restrict__ in, const float* __restrict__ kern,
                              float* __restrict__ out) {
    int idx = blockIdx.x * blockDim.x + threadIdx.x;
    if (idx >= (NPIX / 4) * HID) return;
    int c = idx % HID;
    int strip = idx / HID;
    int xs = (strip & 63) * 4;
    int y  = (strip >> 6) & 255;
    int b  = strip >> 14;

    float accA[4] = {0.f, 0.f, 0.f, 0.f};
    float accB[4] = {0.f, 0.f, 0.f, 0.f};

    #pragma unroll
    for (int dy = -1; dy <= 1; dy++) {
        int yy = y + dy;
        if (yy < 0 || yy > 255) continue;
        const float* rowp = in + ((size_t)((b << 8) + yy) << 8) * H2;
        float va[6], vb[6];
        #pragma unroll
        for (int j = 0; j < 6; j++) {
            int xx = xs - 1 + j;
            if (xx >= 0 && xx <= 255) {
                const float* pp = rowp + (size_t)xx * H2;
                va[j] = pp[c];
                vb[j] = pp[c + HID];
            } else {
                va[j] = 0.f; vb[j] = 0.f;
            }
        }
        #pragma unroll
        for (int dx = 0; dx < 3; dx++) {
            size_t koff = (size_t)((dy + 1) * 3 + dx) * H2;
            float ka = kern[koff + c];
            float kb = kern[koff + c + HID];
            #pragma unroll
            for (int ox = 0; ox < 4; ox++) {
                accA[ox] += va[ox + dx] * ka;
                accB[ox] += vb[ox + dx] * kb;
            }
        }
    }
    size_t pbase = (size_t)((b << 16) + (y << 8) + xs);
    #pragma unroll
    for (int ox = 0; ox < 4; ox++)
        out[(pbase + ox) * HIDP + c] = gelu_exact(accA[ox]) * accB[ox];
    if (c == 0) {
        #pragma unroll
        for (int ox = 0; ox < 4; ox++) out[(pbase + ox) * HIDP + 255] = 0.f;
    }
}

// ---------------- launcher ----------------
extern "C" void kernel_launch(void* const* d_in, const int* in_sizes, int n_in,
                              void* d_out, int out_size) {
    const float* x     = (const float*)d_in[0];
    const float* ln1g  = (const float*)d_in[1];
    const float* ln1b  = (const float*)d_in[2];
    const float* ln2g  = (const float*)d_in[3];
    const float* ln2b  = (const float*)d_in[4];
    const float* qkvw  = (const float*)d_in[5];
    const float* qkvdw = (const float*)d_in[6];
    const float* temp  = (const float*)d_in[7];
    const float* aow   = (const float*)d_in[8];
    const float* fiw   = (const float*)d_in[9];
    const float* fdw   = (const float*)d_in[10];
    const float* fow   = (const float*)d_in[11];
    float* out = (float*)d_out;

    float *t0, *t1, *t2, *gt, *y, *x2, *nrm, *att;
    cudaGetSymbolAddress((void**)&t0,  g_t0);
    cudaGetSymbolAddress((void**)&t1,  g_t1);
    cudaGetSymbolAddress((void**)&t2,  g_t2);
    cudaGetSymbolAddress((void**)&gt,  g_gt);
    cudaGetSymbolAddress((void**)&y,   g_y);
    cudaGetSymbolAddress((void**)&x2,  g_x2);
    cudaGetSymbolAddress((void**)&nrm, g_nrm);
    cudaGetSymbolAddress((void**)&att, g_att);

    // attention branch
    init_kernel<<<1, 256>>>(nrm, att);
    ln_kernel<<<2048, 256>>>(x, ln1g, ln1b, y);
    gemm_tf32_kernel<<<dim3(5, 1024), 256>>>(y, qkvw, nullptr, t0, CDIM, CDIM, QKV);
    dwconv288_kernel<<<9216, 256>>>(t0, qkvdw, t1);
    norms_kernel<<<dim3(64, 2), 192>>>(t1, nrm);
    qkt_kernel<<<dim3(32, 4), 256>>>(t1, att);
    softmax_kernel<<<4, 64>>>(att, nrm, temp);
    attnapply_kernel<<<dim3(2048, 2), 256>>>(t1, att, y);
    gemm_tf32_kernel<<<dim3(2, 1024), 256>>>(y, aow, x, x2, CDIM, CDIM, CDIM);

    // FFN branch
    ln_kernel<<<2048, 256>>>(x2, ln2g, ln2b, y);
    gemm_tf32_kernel<<<dim3(8, 1024), 256>>>(y, fiw, nullptr, t2, CDIM, CDIM, H2);
    dwgate_kernel<<<32640, 256>>>(t2, fdw, gt);
    gemm_tf32_kernel<<<dim3(2, 1024), 256>>>(gt, fow, x2, out, HIDP, HID, CDIM);
}

// round 3
// speedup vs baseline: 1.5978x; 1.2275x over previous
#include <cuda_runtime.h>
#include <cuda_bf16.h>
#include <math.h>
#include <stdint.h>

// ---------------- problem constants ----------------
#define BATCH 2
#define HH 256
#define WW 256
#define CDIM 96
#define HEADS 2
#define CH 48
#define QKV 288
#define HID 255
#define HIDP 256               // padded stride for gated buffer
#define H2 510
#define NPIX 131072            // BATCH*HH*WW

// ---------------- device scratch ----------------
__device__ float g_t0[(size_t)NPIX * QKV];            // qkv pre-dwconv (f32)
__device__ float g_t1[(size_t)NPIX * QKV];            // qkv post-dwconv (f32)
__device__ float g_t2[(size_t)NPIX * H2];             // ffn hidden pre-dwconv (f32)
__device__ __nv_bfloat16 g_ybf[(size_t)NPIX * CDIM];  // LN out / attn-o (bf16 GEMM A)
__device__ __nv_bfloat16 g_gtbf[(size_t)NPIX * HIDP]; // gated (bf16, padded stride 256)
__device__ float g_x2[(size_t)NPIX * CDIM];           // x after attention residual
__device__ float g_nrm[2 * BATCH * CDIM];
__device__ float g_att[BATCH * HEADS * CH * CH];
// bf16 weight copies
__device__ __nv_bfloat16 g_wq[CDIM * QKV];
__device__ __nv_bfloat16 g_wa[CDIM * CDIM];
__device__ __nv_bfloat16 g_wi[CDIM * H2];
__device__ __nv_bfloat16 g_wo[HID * CDIM];

// ---------------- helpers ----------------
__device__ __forceinline__ float gelu_exact(float v) {
    return 0.5f * v * (1.0f + erff(v * 0.70710678118654752f));
}
__device__ __forceinline__ void ldsm_x4(uint32_t* r, uint32_t addr) {
    asm volatile("ldmatrix.sync.aligned.m8n8.x4.shared.b16 {%0,%1,%2,%3}, [%4];"
        : "=r"(r[0]), "=r"(r[1]), "=r"(r[2]), "=r"(r[3]) : "r"(addr));
}
__device__ __forceinline__ void ldsm_x4_t(uint32_t* r, uint32_t addr) {
    asm volatile("ldmatrix.sync.aligned.m8n8.x4.trans.shared.b16 {%0,%1,%2,%3}, [%4];"
        : "=r"(r[0]), "=r"(r[1]), "=r"(r[2]), "=r"(r[3]) : "r"(addr));
}
__device__ __forceinline__ void mma_bf16(float* c, const uint32_t* a, const uint32_t* b) {
    asm volatile("mma.sync.aligned.m16n8k16.row.col.f32.bf16.bf16.f32 "
        "{%0,%1,%2,%3}, {%4,%5,%6,%7}, {%8,%9}, {%0,%1,%2,%3};\n"
        : "+f"(c[0]), "+f"(c[1]), "+f"(c[2]), "+f"(c[3])
        : "r"(a[0]), "r"(a[1]), "r"(a[2]), "r"(a[3]), "r"(b[0]), "r"(b[1]));
}

// ---------------- weight convert f32 -> bf16 ----------------
__global__ void cvt_kernel(const float* __restrict__ s, __nv_bfloat16* __restrict__ d, int n) {
    int i = blockIdx.x * blockDim.x + threadIdx.x;
    if (i < n) d[i] = __float2bfloat16_rn(s[i]);
}

// ---------------- init: zero accumulators ----------------
__global__ void init_kernel(float* nrm, float* attn) {
    int t = threadIdx.x;
    for (int i = t; i < 2 * BATCH * CDIM; i += blockDim.x) nrm[i] = 0.f;
    for (int i = t; i < BATCH * HEADS * CH * CH; i += blockDim.x) attn[i] = 0.f;
}

// ---------------- per-pixel LayerNorm -> bf16, warp per pixel ----------------
__global__ void ln_kernel(const float* __restrict__ in, const float* __restrict__ gamma,
                          const float* __restrict__ beta, __nv_bfloat16* __restrict__ out) {
    int warp = blockIdx.x * (blockDim.x >> 5) + (threadIdx.x >> 5);
    int lane = threadIdx.x & 31;
    int nwarps = gridDim.x * (blockDim.x >> 5);
    float g0 = gamma[lane], g1 = gamma[lane + 32], g2 = gamma[lane + 64];
    float b0 = beta[lane],  b1 = beta[lane + 32],  b2 = beta[lane + 64];
    for (int p = warp; p < NPIX; p += nwarps) {
        const float* xp = in + (size_t)p * CDIM;
        float v0 = xp[lane], v1 = xp[lane + 32], v2 = xp[lane + 64];
        float s  = v0 + v1 + v2;
        float ss = v0 * v0 + v1 * v1 + v2 * v2;
        #pragma unroll
        for (int o = 16; o > 0; o >>= 1) {
            s  += __shfl_xor_sync(0xffffffffu, s,  o);
            ss += __shfl_xor_sync(0xffffffffu, ss, o);
        }
        float mu = s * (1.f / 96.f);
        float var = ss * (1.f / 96.f) - mu * mu;
        float rstd = rsqrtf(var + 1e-5f);
        __nv_bfloat16* yp = out + (size_t)p * CDIM;
        yp[lane]      = __float2bfloat16_rn((v0 - mu) * rstd * g0 + b0);
        yp[lane + 32] = __float2bfloat16_rn((v1 - mu) * rstd * g1 + b1);
        yp[lane + 64] = __float2bfloat16_rn((v2 - mu) * rstd * g2 + b2);
    }
}

// ---------------- bf16 tensor-core GEMM: C[M,N](f32) = A[M,Ka] * B[Kb,N] (+R) ----------------
// BM=128, BN=64, BK=32, 256 threads, 8 warps (4M x 2N), warp tile 32x32 via m16n8k16.
// Ka: A row stride & padded K (multiple of 32, pad zeros). Kb: real K rows of B.
__global__ void __launch_bounds__(256)
gemm_bf16_kernel(const __nv_bfloat16* __restrict__ A, const __nv_bfloat16* __restrict__ Bw,
                 const float* __restrict__ R, float* __restrict__ C,
                 int Ka, int Kb, int N) {
    __shared__ __align__(16) __nv_bfloat16 As[128][40];  // pad 8 -> 80B rows
    __shared__ __align__(16) __nv_bfloat16 Bs[32][72];   // pad 8 -> 144B rows
    int tid = threadIdx.x;
    int m0 = blockIdx.y * 128;
    int n0 = blockIdx.x * 64;
    int lane = tid & 31, warp = tid >> 5;
    int g = lane >> 2, tg = lane & 3;
    int warpM = warp & 3, warpN = warp >> 2;
    int mbase = warpM * 32, nbase = warpN * 32;

    float acc[2][4][4];
    #pragma unroll
    for (int mt = 0; mt < 2; mt++)
        #pragma unroll
        for (int nt = 0; nt < 4; nt++)
            #pragma unroll
            for (int i = 0; i < 4; i++) acc[mt][nt][i] = 0.f;

    // precompute ldmatrix smem addresses
    uint32_t a_addr[2], b_addr[2];
    {
        int arow = (lane & 15);
        int acol = (lane >> 4) << 3;
        #pragma unroll
        for (int mt = 0; mt < 2; mt++)
            a_addr[mt] = (uint32_t)__cvta_generic_to_shared(&As[mbase + mt * 16 + arow][acol]);
        int krow = ((lane >> 3) & 1) * 8 + (lane & 7);
        int coff = (lane >> 4) << 3;
        #pragma unroll
        for (int nh = 0; nh < 2; nh++)
            b_addr[nh] = (uint32_t)__cvta_generic_to_shared(&Bs[krow][nbase + nh * 16 + coff]);
    }

    int Kt = Ka >> 5;
    for (int kb = 0; kb < Kt; kb++) {
        int k0 = kb << 5;
        // A tile: 128x32 bf16 = 1024 uint2
        #pragma unroll
        for (int l = 0; l < 4; l++) {
            int idx = tid + l * 256;
            int row = idx >> 3, q = (idx & 7) << 2;
            *(uint2*)&As[row][q] = *(const uint2*)(A + (size_t)(m0 + row) * Ka + k0 + q);
        }
        // B tile: 32x64 bf16 = 1024 uint (guarded)
        #pragma unroll
        for (int l = 0; l < 4; l++) {
            int idx = tid + l * 256;
            int row = idx >> 5, nu = idx & 31;
            int kk = k0 + row, col = n0 + nu * 2;
            uint32_t v = 0;
            if (kk < Kb && col < N) v = *(const uint32_t*)(Bw + (size_t)kk * N + col);
            *(uint32_t*)&Bs[row][nu * 2] = v;
        }
        __syncthreads();
        #pragma unroll
        for (int ks = 0; ks < 2; ks++) {
            int k16 = ks << 4;
            uint32_t af[2][4], bq[2][4];
            #pragma unroll
            for (int mt = 0; mt < 2; mt++)
                ldsm_x4(af[mt], a_addr[mt] + k16 * 2);
            #pragma unroll
            for (int nh = 0; nh < 2; nh++)
                ldsm_x4_t(bq[nh], b_addr[nh] + k16 * 144);
            #pragma unroll
            for (int mt = 0; mt < 2; mt++) {
                #pragma unroll
                for (int nh = 0; nh < 2; nh++) {
                    mma_bf16(acc[mt][nh * 2 + 0], af[mt], &bq[nh][0]);
                    mma_bf16(acc[mt][nh * 2 + 1], af[mt], &bq[nh][2]);
                }
            }
        }
        __syncthreads();
    }
    // epilogue
    #pragma unroll
    for (int mt = 0; mt < 2; mt++) {
        #pragma unroll
        for (int nt = 0; nt < 4; nt++) {
            #pragma unroll
            for (int i = 0; i < 4; i++) {
                int row = mbase + mt * 16 + g + ((i >> 1) << 3);
                int col = nbase + nt * 8 + tg * 2 + (i & 1);
                int n = n0 + col;
                if (n < N) {
                    size_t o = (size_t)(m0 + row) * N + n;
                    float v = acc[mt][nt][i];
                    if (R) v += R[o];
                    C[o] = v;
                }
            }
        }
    }
}

// ---------------- depthwise 3x3, C=288, float4 channels, 4-wide x strip ----------------
__global__ void dwconv288_kernel(const float* __restrict__ in, const float* __restrict__ kern,
                                 float* __restrict__ out) {
    const int C4 = QKV / 4; // 72
    int idx = blockIdx.x * blockDim.x + threadIdx.x;
    if (idx >= (NPIX / 4) * C4) return;
    int c4 = idx % C4;
    int strip = idx / C4;
    int xs = (strip & 63) * 4;
    int y  = (strip >> 6) & 255;
    int b  = strip >> 14;

    float4 acc[4];
    #pragma unroll
    for (int ox = 0; ox < 4; ox++) acc[ox] = make_float4(0.f, 0.f, 0.f, 0.f);

    #pragma unroll
    for (int dy = -1; dy <= 1; dy++) {
        int yy = y + dy;
        if (yy < 0 || yy > 255) continue;
        const float* rowp = in + ((size_t)((b << 8) + yy) << 8) * QKV;
        float4 v[6];
        #pragma unroll
        for (int j = 0; j < 6; j++) {
            int xx = xs - 1 + j;
            if (xx >= 0 && xx <= 255)
                v[j] = *(const float4*)(rowp + (size_t)xx * QKV + c4 * 4);
            else
                v[j] = make_float4(0.f, 0.f, 0.f, 0.f);
        }
        #pragma unroll
        for (int dx = 0; dx < 3; dx++) {
            float4 kv = *(const float4*)(kern + (size_t)((dy + 1) * 3 + dx) * QKV + c4 * 4);
            #pragma unroll
            for (int ox = 0; ox < 4; ox++) {
                acc[ox].x += v[ox + dx].x * kv.x;
                acc[ox].y += v[ox + dx].y * kv.y;
                acc[ox].z += v[ox + dx].z * kv.z;
                acc[ox].w += v[ox + dx].w * kv.w;
            }
        }
    }
    float* op = out + ((size_t)((b << 16) + (y << 8) + xs)) * QKV + c4 * 4;
    #pragma unroll
    for (int ox = 0; ox < 4; ox++) *(float4*)(op + (size_t)ox * QKV) = acc[ox];
}

// ---------------- q/k sum-of-squares over spatial ----------------
__global__ void norms_kernel(const float* __restrict__ t1, float* __restrict__ nrm) {
    int b = blockIdx.y;
    int c = threadIdx.x;             // 0..191
    int s0 = blockIdx.x * 1024;
    const float* base = t1 + ((size_t)(b << 16) + s0) * QKV + c;
    float acc = 0.f;
    for (int s = 0; s < 1024; s++) {
        float v = base[(size_t)s * QKV];
        acc += v * v;
    }
    atomicAdd(&nrm[b * 192 + c], acc);
}

// ---------------- raw q*k^T accumulation ----------------
__global__ void qkt_kernel(const float* __restrict__ t1, float* __restrict__ attn) {
    __shared__ float qs[16][48];
    __shared__ float ks[16][48];
    int bh = blockIdx.y;
    int b = bh >> 1, hd = bh & 1;
    int s0 = blockIdx.x * 2048;
    int tid = threadIdx.x;
    int tx = tid & 15, ty = tid >> 4;
    float acc[3][3];
    #pragma unroll
    for (int r = 0; r < 3; r++)
        #pragma unroll
        for (int c = 0; c < 3; c++) acc[r][c] = 0.f;

    const float* qbase = t1 + ((size_t)(b << 16)) * QKV + hd * CH;
    const float* kbase = qbase + CDIM;
    for (int st = 0; st < 2048; st += 16) {
        #pragma unroll
        for (int l = 0; l < 3; l++) {
            int idx = tid + l * 256;
            int si = idx / 48, e = idx % 48;
            size_t off = (size_t)(s0 + st + si) * QKV + e;
            qs[si][e] = qbase[off];
            ks[si][e] = kbase[off];
        }
        __syncthreads();
        #pragma unroll
        for (int si = 0; si < 16; si++) {
            float qv[3], kv[3];
            #pragma unroll
            for (int r = 0; r < 3; r++) qv[r] = qs[si][ty * 3 + r];
            #pragma unroll
            for (int c = 0; c < 3; c++) kv[c] = ks[si][tx * 3 + c];
            #pragma unroll
            for (int r = 0; r < 3; r++)
                #pragma unroll
                for (int c = 0; c < 3; c++) acc[r][c] += qv[r] * kv[c];
        }
        __syncthreads();
    }
    float* ab = attn + (size_t)bh * CH * CH;
    #pragma unroll
    for (int r = 0; r < 3; r++)
        #pragma unroll
        for (int c = 0; c < 3; c++)
            atomicAdd(&ab[(ty * 3 + r) * CH + (tx * 3 + c)], acc[r][c]);
}

// ---------------- normalize + temperature + softmax ----------------
__global__ void softmax_kernel(float* __restrict__ attn, const float* __restrict__ nrm,
                               const float* __restrict__ temp) {
    int bh = blockIdx.x;
    int b = bh >> 1, hd = bh & 1;
    int d = threadIdx.x;
    if (d >= CH) return;
    float t = temp[hd];
    float rq = rsqrtf(nrm[b * 192 + hd * CH + d]);
    float* row = attn + (size_t)bh * CH * CH + d * CH;
    float vals[CH];
    float mx = -1e30f;
    #pragma unroll
    for (int e = 0; e < CH; e++) {
        float rk = rsqrtf(nrm[b * 192 + CDIM + hd * CH + e]);
        float v = row[e] * rq * rk * t;
        vals[e] = v;
        mx = fmaxf(mx, v);
    }
    float s = 0.f;
    #pragma unroll
    for (int e = 0; e < CH; e++) { vals[e] = expf(vals[e] - mx); s += vals[e]; }
    float inv = 1.f / s;
    #pragma unroll
    for (int e = 0; e < CH; e++) row[e] = vals[e] * inv;
}

// ---------------- o = attn @ v (bf16 out) ----------------
__global__ void attnapply_kernel(const float* __restrict__ t1, const float* __restrict__ attn,
                                 __nv_bfloat16* __restrict__ o) {
    __shared__ float at[HEADS * CH * CH];
    __shared__ float vs[32][CDIM];
    int b = blockIdx.y;
    int p0 = blockIdx.x * 32;
    int tid = threadIdx.x;
    for (int i = tid; i < HEADS * CH * CH; i += 256) at[i] = attn[(size_t)b * HEADS * CH * CH + i];
    const float* vbase = t1 + ((size_t)((b << 16) + p0)) * QKV + 2 * CDIM;
    #pragma unroll
    for (int l = 0; l < 12; l++) {
        int idx = tid + l * 256;
        int p = idx / CDIM, c = idx % CDIM;
        vs[p][c] = vbase[(size_t)p * QKV + c];
    }
    __syncthreads();
    __nv_bfloat16* obase = o + ((size_t)((b << 16) + p0)) * CDIM;
    #pragma unroll
    for (int l = 0; l < 12; l++) {
        int idx = tid + l * 256;
        int p = idx / CDIM, c = idx % CDIM;
        int hd = c / CH, cm = c % CH;
        const float* arow = &at[(hd * CH + cm) * CH];
        const float* vrow = &vs[p][hd * CH];
        float s = 0.f;
        #pragma unroll
        for (int e = 0; e < CH; e++) s += arow[e] * vrow[e];
        obase[(size_t)p * CDIM + c] = __float2bfloat16_rn(s);
    }
}

// ---------------- depthwise 3x3 on 510ch + GELU gate -> bf16 255ch (stride-256) ----------------
__global__ void dwgate_kernel(const float* __restrict__ in, const float* __restrict__ kern,
                              __nv_bfloat16* __restrict__ out) {
    int idx = blockIdx.x * blockDim.x + threadIdx.x;
    if (idx >= (NPIX / 4) * HID) return;
    int c = idx % HID;
    int strip = idx / HID;
    int xs = (strip & 63) * 4;
    int y  = (strip >> 6) & 255;
    int b  = strip >> 14;

    float accA[4] = {0.f, 0.f, 0.f, 0.f};
    float accB[4] = {0.f, 0.f, 0.f, 0.f};

    #pragma unroll
    for (int dy = -1; dy <= 1; dy++) {
        int yy = y + dy;
        if (yy < 0 || yy > 255) continue;
        const float* rowp = in + ((size_t)((b << 8) + yy) << 8) * H2;
        float va[6], vb[6];
        #pragma unroll
        for (int j = 0; j < 6; j++) {
            int xx = xs - 1 + j;
            if (xx >= 0 && xx <= 255) {
                const float* pp = rowp + (size_t)xx * H2;
                va[j] = pp[c];
                vb[j] = pp[c + HID];
            } else {
                va[j] = 0.f; vb[j] = 0.f;
            }
        }
        #pragma unroll
        for (int dx = 0; dx < 3; dx++) {
            size_t koff = (size_t)((dy + 1) * 3 + dx) * H2;
            float ka = kern[koff + c];
            float kb = kern[koff + c + HID];
            #pragma unroll
            for (int ox = 0; ox < 4; ox++) {
                accA[ox] += va[ox + dx] * ka;
                accB[ox] += vb[ox + dx] * kb;
            }
        }
    }
    size_t pbase = (size_t)((b << 16) + (y << 8) + xs);
    #pragma unroll
    for (int ox = 0; ox < 4; ox++)
        out[(pbase + ox) * HIDP + c] = __float2bfloat16_rn(gelu_exact(accA[ox]) * accB[ox]);
    if (c == 0) {
        #pragma unroll
        for (int ox = 0; ox < 4; ox++) out[(pbase + ox) * HIDP + 255] = __float2bfloat16_rn(0.f);
    }
}

// ---------------- launcher ----------------
extern "C" void kernel_launch(void* const* d_in, const int* in_sizes, int n_in,
                              void* d_out, int out_size) {
    const float* x     = (const float*)d_in[0];
    const float* ln1g  = (const float*)d_in[1];
    const float* ln1b  = (const float*)d_in[2];
    const float* ln2g  = (const float*)d_in[3];
    const float* ln2b  = (const float*)d_in[4];
    const float* qkvw  = (const float*)d_in[5];
    const float* qkvdw = (const float*)d_in[6];
    const float* temp  = (const float*)d_in[7];
    const float* aow   = (const float*)d_in[8];
    const float* fiw   = (const float*)d_in[9];
    const float* fdw   = (const float*)d_in[10];
    const float* fow   = (const float*)d_in[11];
    float* out = (float*)d_out;

    float *t0, *t1, *t2, *x2, *nrm, *att;
    __nv_bfloat16 *ybf, *gtbf, *wq, *wa, *wi, *wo;
    cudaGetSymbolAddress((void**)&t0,   g_t0);
    cudaGetSymbolAddress((void**)&t1,   g_t1);
    cudaGetSymbolAddress((void**)&t2,   g_t2);
    cudaGetSymbolAddress((void**)&ybf,  g_ybf);
    cudaGetSymbolAddress((void**)&gtbf, g_gtbf);
    cudaGetSymbolAddress((void**)&x2,   g_x2);
    cudaGetSymbolAddress((void**)&nrm,  g_nrm);
    cudaGetSymbolAddress((void**)&att,  g_att);
    cudaGetSymbolAddress((void**)&wq,   g_wq);
    cudaGetSymbolAddress((void**)&wa,   g_wa);
    cudaGetSymbolAddress((void**)&wi,   g_wi);
    cudaGetSymbolAddress((void**)&wo,   g_wo);

    // weight conversion (tiny)
    cvt_kernel<<<(CDIM * QKV + 255) / 256, 256>>>(qkvw, wq, CDIM * QKV);
    cvt_kernel<<<(CDIM * CDIM + 255) / 256, 256>>>(aow, wa, CDIM * CDIM);
    cvt_kernel<<<(CDIM * H2 + 255) / 256, 256>>>(fiw, wi, CDIM * H2);
    cvt_kernel<<<(HID * CDIM + 255) / 256, 256>>>(fow, wo, HID * CDIM);

    // attention branch
    init_kernel<<<1, 256>>>(nrm, att);
    ln_kernel<<<2048, 256>>>(x, ln1g, ln1b, ybf);
    gemm_bf16_kernel<<<dim3(5, 1024), 256>>>(ybf, wq, nullptr, t0, CDIM, CDIM, QKV);
    dwconv288_kernel<<<9216, 256>>>(t0, qkvdw, t1);
    norms_kernel<<<dim3(64, 2), 192>>>(t1, nrm);
    qkt_kernel<<<dim3(32, 4), 256>>>(t1, att);
    softmax_kernel<<<4, 64>>>(att, nrm, temp);
    attnapply_kernel<<<dim3(2048, 2), 256>>>(t1, att, ybf);
    gemm_bf16_kernel<<<dim3(2, 1024), 256>>>(ybf, wa, x, x2, CDIM, CDIM, CDIM);

    // FFN branch
    ln_kernel<<<2048, 256>>>(x2, ln2g, ln2b, ybf);
    gemm_bf16_kernel<<<dim3(8, 1024), 256>>>(ybf, wi, nullptr, t2, CDIM, CDIM, H2);
    dwgate_kernel<<<32640, 256>>>(t2, fdw, gtbf);
    gemm_bf16_kernel<<<dim3(2, 1024), 256>>>(gtbf, wo, x2, out, HIDP, HID, CDIM);
}

// round 4
// speedup vs baseline: 2.0434x; 1.2789x over previous
#include <cuda_runtime.h>
#include <cuda_bf16.h>
#include <math.h>
#include <stdint.h>

// ---------------- problem constants ----------------
#define BATCH 2
#define CDIM 96
#define HEADS 2
#define CH 48
#define QKV 288
#define HID 255
#define HIDP 256
#define H2 510
#define NPIX 131072

typedef __nv_bfloat16 bf16;

// ---------------- device scratch ----------------
__device__ bf16 g_t0[(size_t)NPIX * QKV];    // qkv pre-dwconv
__device__ bf16 g_t1[(size_t)NPIX * QKV];    // qkv post-dwconv
__device__ bf16 g_t2[(size_t)NPIX * H2];     // ffn hidden pre-dwconv
__device__ bf16 g_gt[(size_t)NPIX * HIDP];   // gated (padded stride 256)
__device__ bf16 g_ybf[(size_t)NPIX * CDIM];  // LN out / attn-o
__device__ float g_x2[(size_t)NPIX * CDIM];  // x after attention residual
__device__ float g_nrm[2 * BATCH * CDIM];
__device__ float g_att[BATCH * HEADS * CH * CH];
__device__ bf16 g_wq[CDIM * QKV];
__device__ bf16 g_wa[CDIM * CDIM];
__device__ bf16 g_wi[CDIM * H2];
__device__ bf16 g_wo[HID * CDIM];

// ---------------- helpers ----------------
__device__ __forceinline__ float gelu_exact(float v) {
    return 0.5f * v * (1.0f + erff(v * 0.70710678118654752f));
}
__device__ __forceinline__ void ldsm_x4(uint32_t* r, uint32_t addr) {
    asm volatile("ldmatrix.sync.aligned.m8n8.x4.shared.b16 {%0,%1,%2,%3}, [%4];"
        : "=r"(r[0]), "=r"(r[1]), "=r"(r[2]), "=r"(r[3]) : "r"(addr));
}
__device__ __forceinline__ void ldsm_x4_t(uint32_t* r, uint32_t addr) {
    asm volatile("ldmatrix.sync.aligned.m8n8.x4.trans.shared.b16 {%0,%1,%2,%3}, [%4];"
        : "=r"(r[0]), "=r"(r[1]), "=r"(r[2]), "=r"(r[3]) : "r"(addr));
}
__device__ __forceinline__ void mma_bf16(float* c, const uint32_t* a, const uint32_t* b) {
    asm volatile("mma.sync.aligned.m16n8k16.row.col.f32.bf16.bf16.f32 "
        "{%0,%1,%2,%3}, {%4,%5,%6,%7}, {%8,%9}, {%0,%1,%2,%3};\n"
        : "+f"(c[0]), "+f"(c[1]), "+f"(c[2]), "+f"(c[3])
        : "r"(a[0]), "r"(a[1]), "r"(a[2]), "r"(a[3]), "r"(b[0]), "r"(b[1]));
}
__device__ __forceinline__ uint32_t pack_bf2(float a, float b) {
    __nv_bfloat162 h = __floats2bfloat162_rn(a, b);
    return *(uint32_t*)&h;
}

// ---------------- all weight converts in one kernel ----------------
__global__ void cvt_all_kernel(const float* wq, const float* wa, const float* wi, const float* wo,
                               bf16* dq, bf16* da, bf16* di, bf16* dxo) {
    int i = blockIdx.x * blockDim.x + threadIdx.x;
    const int s0 = CDIM * QKV, s1 = s0 + CDIM * CDIM, s2 = s1 + CDIM * H2, s3 = s2 + HID * CDIM;
    if (i < s0) dq[i] = __float2bfloat16_rn(wq[i]);
    else if (i < s1) da[i - s0] = __float2bfloat16_rn(wa[i - s0]);
    else if (i < s2) di[i - s1] = __float2bfloat16_rn(wi[i - s1]);
    else if (i < s3) dxo[i - s2] = __float2bfloat16_rn(wo[i - s2]);
}

__global__ void init_kernel(float* nrm, float* attn) {
    int t = threadIdx.x;
    for (int i = t; i < 2 * BATCH * CDIM; i += blockDim.x) nrm[i] = 0.f;
    for (int i = t; i < BATCH * HEADS * CH * CH; i += blockDim.x) attn[i] = 0.f;
}

// ---------------- per-pixel LayerNorm -> bf16 ----------------
__global__ void ln_kernel(const float* __restrict__ in, const float* __restrict__ gamma,
                          const float* __restrict__ beta, bf16* __restrict__ out) {
    int warp = blockIdx.x * (blockDim.x >> 5) + (threadIdx.x >> 5);
    int lane = threadIdx.x & 31;
    int nwarps = gridDim.x * (blockDim.x >> 5);
    float g0 = gamma[lane], g1 = gamma[lane + 32], g2 = gamma[lane + 64];
    float b0 = beta[lane],  b1 = beta[lane + 32],  b2 = beta[lane + 64];
    for (int p = warp; p < NPIX; p += nwarps) {
        const float* xp = in + (size_t)p * CDIM;
        float v0 = xp[lane], v1 = xp[lane + 32], v2 = xp[lane + 64];
        float s  = v0 + v1 + v2;
        float ss = v0 * v0 + v1 * v1 + v2 * v2;
        #pragma unroll
        for (int o = 16; o > 0; o >>= 1) {
            s  += __shfl_xor_sync(0xffffffffu, s,  o);
            ss += __shfl_xor_sync(0xffffffffu, ss, o);
        }
        float mu = s * (1.f / 96.f);
        float var = ss * (1.f / 96.f) - mu * mu;
        float rstd = rsqrtf(var + 1e-5f);
        bf16* yp = out + (size_t)p * CDIM;
        yp[lane]      = __float2bfloat16_rn((v0 - mu) * rstd * g0 + b0);
        yp[lane + 32] = __float2bfloat16_rn((v1 - mu) * rstd * g1 + b1);
        yp[lane + 64] = __float2bfloat16_rn((v2 - mu) * rstd * g2 + b2);
    }
}

// ---------------- templated bf16 tensor-core GEMM ----------------
// C[M,N] = A[M,Ka] * B[Kb,N] (+R). BM=128, BN=NT*16, 8 warps (4M x 2N).
// KITER k-chunks of BK. A stride Ka = KITER*BK (zero-padded OK). B guarded by Kb,N.
template<int NT, int BK, int KITER, bool BF16OUT>
__global__ void __launch_bounds__(256)
gemm_k(const bf16* __restrict__ A, const bf16* __restrict__ Bw,
       const float* __restrict__ R, void* __restrict__ Cout,
       int Ka, int Kb, int N) {
    constexpr int BN = NT * 16;
    constexpr int PA = BK + 8;
    constexpr int PB = BN + 8;
    __shared__ __align__(16) bf16 As[128][PA];
    __shared__ __align__(16) bf16 Bs[BK][PB];

    int tid = threadIdx.x;
    int m0 = blockIdx.y * 128;
    int n0 = blockIdx.x * BN;
    int lane = tid & 31, warp = tid >> 5;
    int g = lane >> 2, tg = lane & 3;
    int warpM = warp & 3, warpN = warp >> 2;
    int mbase = warpM * 32, nbase = warpN * (NT * 8);

    float acc[2][NT][4];
    #pragma unroll
    for (int mt = 0; mt < 2; mt++)
        #pragma unroll
        for (int nt = 0; nt < NT; nt++)
            #pragma unroll
            for (int i = 0; i < 4; i++) acc[mt][nt][i] = 0.f;

    uint32_t a_addr[2], b_addr[NT / 2];
    {
        int arow = lane & 15;
        int acol = (lane >> 4) << 3;
        #pragma unroll
        for (int mt = 0; mt < 2; mt++)
            a_addr[mt] = (uint32_t)__cvta_generic_to_shared(&As[mbase + mt * 16 + arow][acol]);
        int krow = ((lane >> 3) & 1) * 8 + (lane & 7);
        int coff = (lane >> 4) << 3;
        #pragma unroll
        for (int nh = 0; nh < NT / 2; nh++)
            b_addr[nh] = (uint32_t)__cvta_generic_to_shared(&Bs[krow][nbase + nh * 16 + coff]);
    }

    #pragma unroll
    for (int kit = 0; kit < KITER; kit++) {
        int k0 = kit * BK;
        // A tile: 128 x BK bf16 via uint4 (8 bf16)
        constexpr int AC = BK / 8;           // chunks per row
        constexpr int AL = 128 * AC / 256;   // per-thread chunks
        #pragma unroll
        for (int l = 0; l < AL; l++) {
            int idx = tid + l * 256;
            int row = idx / AC, c8 = idx % AC;
            *(uint4*)&As[row][c8 * 8] =
                *(const uint4*)(A + (size_t)(m0 + row) * Ka + k0 + c8 * 8);
        }
        // B tile: BK x BN bf16 via uint32 (2 cols), guarded
        constexpr int BC = BN / 2;
        constexpr int BL = BK * BC / 256;
        #pragma unroll
        for (int l = 0; l < BL; l++) {
            int idx = tid + l * 256;
            int row = idx / BC, nu = idx % BC;
            int kk = k0 + row, col = n0 + nu * 2;
            uint32_t v = 0;
            if (kk < Kb && col < N) v = *(const uint32_t*)(Bw + (size_t)kk * N + col);
            *(uint32_t*)&Bs[row][nu * 2] = v;
        }
        __syncthreads();
        #pragma unroll
        for (int ks = 0; ks < BK / 16; ks++) {
            uint32_t af[2][4];
            #pragma unroll
            for (int mt = 0; mt < 2; mt++)
                ldsm_x4(af[mt], a_addr[mt] + ks * 32);
            #pragma unroll
            for (int nh = 0; nh < NT / 2; nh++) {
                uint32_t bq[4];
                ldsm_x4_t(bq, b_addr[nh] + ks * 16 * (PB * 2));
                #pragma unroll
                for (int mt = 0; mt < 2; mt++) {
                    mma_bf16(acc[mt][nh * 2 + 0], af[mt], &bq[0]);
                    mma_bf16(acc[mt][nh * 2 + 1], af[mt], &bq[2]);
                }
            }
        }
        if (kit + 1 < KITER) __syncthreads();
    }

    // epilogue: paired stores (cols tg*2, tg*2+1)
    #pragma unroll
    for (int mt = 0; mt < 2; mt++) {
        #pragma unroll
        for (int nt = 0; nt < NT; nt++) {
            int col = n0 + nbase + nt * 8 + tg * 2;
            if (col >= N) continue;
            #pragma unroll
            for (int h = 0; h < 2; h++) {
                int row = m0 + mbase + mt * 16 + g + h * 8;
                size_t o = (size_t)row * N + col;
                float v0 = acc[mt][nt][h * 2 + 0];
                float v1 = acc[mt][nt][h * 2 + 1];
                if (R) {
                    float2 r2 = *(const float2*)(R + o);
                    v0 += r2.x; v1 += r2.y;
                }
                if (BF16OUT) {
                    *(uint32_t*)((bf16*)Cout + o) = pack_bf2(v0, v1);
                } else {
                    *(float2*)((float*)Cout + o) = make_float2(v0, v1);
                }
            }
        }
    }
}

// ---------------- depthwise 3x3, C=288 bf16, 8-ch chunks, 4-wide x strip ----------------
__global__ void dwconv288_kernel(const bf16* __restrict__ in, const float* __restrict__ kern,
                                 bf16* __restrict__ out) {
    const int C8 = QKV / 8; // 36
    int idx = blockIdx.x * blockDim.x + threadIdx.x;
    if (idx >= (NPIX / 4) * C8) return;
    int c8 = idx % C8;
    int strip = idx / C8;
    int xs = (strip & 63) * 4;
    int y  = (strip >> 6) & 255;
    int b  = strip >> 14;

    float acc[4][8];
    #pragma unroll
    for (int ox = 0; ox < 4; ox++)
        #pragma unroll
        for (int e = 0; e < 8; e++) acc[ox][e] = 0.f;

    #pragma unroll
    for (int dy = -1; dy <= 1; dy++) {
        int yy = y + dy;
        if (yy < 0 || yy > 255) continue;
        const bf16* rowp = in + ((size_t)((b << 8) + yy) << 8) * QKV;
        float v[6][8];
        #pragma unroll
        for (int j = 0; j < 6; j++) {
            int xx = xs - 1 + j;
            if (xx >= 0 && xx <= 255) {
                uint4 u = *(const uint4*)(rowp + (size_t)xx * QKV + c8 * 8);
                const __nv_bfloat162* p2 = (const __nv_bfloat162*)&u;
                #pragma unroll
                for (int q = 0; q < 4; q++) {
                    float2 f = __bfloat1622float2(p2[q]);
                    v[j][q * 2] = f.x; v[j][q * 2 + 1] = f.y;
                }
            } else {
                #pragma unroll
                for (int e = 0; e < 8; e++) v[j][e] = 0.f;
            }
        }
        #pragma unroll
        for (int dx = 0; dx < 3; dx++) {
            const float* kp = kern + (size_t)((dy + 1) * 3 + dx) * QKV + c8 * 8;
            float kv[8];
            *(float4*)&kv[0] = *(const float4*)kp;
            *(float4*)&kv[4] = *(const float4*)(kp + 4);
            #pragma unroll
            for (int ox = 0; ox < 4; ox++)
                #pragma unroll
                for (int e = 0; e < 8; e++) acc[ox][e] += v[ox + dx][e] * kv[e];
        }
    }
    bf16* op = out + ((size_t)((b << 16) + (y << 8) + xs)) * QKV + c8 * 8;
    #pragma unroll
    for (int ox = 0; ox < 4; ox++) {
        uint4 u;
        uint32_t* w = (uint32_t*)&u;
        #pragma unroll
        for (int q = 0; q < 4; q++) w[q] = pack_bf2(acc[ox][q * 2], acc[ox][q * 2 + 1]);
        *(uint4*)(op + (size_t)ox * QKV) = u;
    }
}

// ---------------- q/k sum-of-squares over spatial ----------------
__global__ void norms_kernel(const bf16* __restrict__ t1, float* __restrict__ nrm) {
    int b = blockIdx.y;
    int c = threadIdx.x;             // 0..191
    int s0 = blockIdx.x * 1024;
    const bf16* base = t1 + ((size_t)(b << 16) + s0) * QKV + c;
    float acc = 0.f;
    for (int s = 0; s < 1024; s++) {
        float v = __bfloat162float(base[(size_t)s * QKV]);
        acc += v * v;
    }
    atomicAdd(&nrm[b * 192 + c], acc);
}

// ---------------- raw q*k^T accumulation ----------------
__global__ void qkt_kernel(const bf16* __restrict__ t1, float* __restrict__ attn) {
    __shared__ float qs[16][48];
    __shared__ float ks[16][48];
    int bh = blockIdx.y;
    int b = bh >> 1, hd = bh & 1;
    int s0 = blockIdx.x * 2048;
    int tid = threadIdx.x;
    int tx = tid & 15, ty = tid >> 4;
    float acc[3][3];
    #pragma unroll
    for (int r = 0; r < 3; r++)
        #pragma unroll
        for (int c = 0; c < 3; c++) acc[r][c] = 0.f;

    const bf16* qbase = t1 + ((size_t)(b << 16)) * QKV + hd * CH;
    const bf16* kbase = qbase + CDIM;
    for (int st = 0; st < 2048; st += 16) {
        #pragma unroll
        for (int l = 0; l < 3; l++) {
            int idx = tid + l * 256;
            int si = idx / 48, e = idx % 48;
            size_t off = (size_t)(s0 + st + si) * QKV + e;
            qs[si][e] = __bfloat162float(qbase[off]);
            ks[si][e] = __bfloat162float(kbase[off]);
        }
        __syncthreads();
        #pragma unroll
        for (int si = 0; si < 16; si++) {
            float qv[3], kv[3];
            #pragma unroll
            for (int r = 0; r < 3; r++) qv[r] = qs[si][ty * 3 + r];
            #pragma unroll
            for (int c = 0; c < 3; c++) kv[c] = ks[si][tx * 3 + c];
            #pragma unroll
            for (int r = 0; r < 3; r++)
                #pragma unroll
                for (int c = 0; c < 3; c++) acc[r][c] += qv[r] * kv[c];
        }
        __syncthreads();
    }
    float* ab = attn + (size_t)bh * CH * CH;
    #pragma unroll
    for (int r = 0; r < 3; r++)
        #pragma unroll
        for (int c = 0; c < 3; c++)
            atomicAdd(&ab[(ty * 3 + r) * CH + (tx * 3 + c)], acc[r][c]);
}

// ---------------- normalize + temperature + softmax ----------------
__global__ void softmax_kernel(float* __restrict__ attn, const float* __restrict__ nrm,
                               const float* __restrict__ temp) {
    int bh = blockIdx.x;
    int b = bh >> 1, hd = bh & 1;
    int d = threadIdx.x;
    if (d >= CH) return;
    float t = temp[hd];
    float rq = rsqrtf(nrm[b * 192 + hd * CH + d]);
    float* row = attn + (size_t)bh * CH * CH + d * CH;
    float vals[CH];
    float mx = -1e30f;
    #pragma unroll
    for (int e = 0; e < CH; e++) {
        float rk = rsqrtf(nrm[b * 192 + CDIM + hd * CH + e]);
        float v = row[e] * rq * rk * t;
        vals[e] = v;
        mx = fmaxf(mx, v);
    }
    float s = 0.f;
    #pragma unroll
    for (int e = 0; e < CH; e++) { vals[e] = expf(vals[e] - mx); s += vals[e]; }
    float inv = 1.f / s;
    #pragma unroll
    for (int e = 0; e < CH; e++) row[e] = vals[e] * inv;
}

// ---------------- o = attn @ v (bf16 in/out) ----------------
__global__ void attnapply_kernel(const bf16* __restrict__ t1, const float* __restrict__ attn,
                                 bf16* __restrict__ o) {
    __shared__ float at[HEADS * CH * CH];
    __shared__ float vs[32][CDIM];
    int b = blockIdx.y;
    int p0 = blockIdx.x * 32;
    int tid = threadIdx.x;
    for (int i = tid; i < HEADS * CH * CH; i += 256) at[i] = attn[(size_t)b * HEADS * CH * CH + i];
    const bf16* vbase = t1 + ((size_t)((b << 16) + p0)) * QKV + 2 * CDIM;
    #pragma unroll
    for (int l = 0; l < 12; l++) {
        int idx = tid + l * 256;
        int p = idx / CDIM, c = idx % CDIM;
        vs[p][c] = __bfloat162float(vbase[(size_t)p * QKV + c]);
    }
    __syncthreads();
    bf16* obase = o + ((size_t)((b << 16) + p0)) * CDIM;
    #pragma unroll
    for (int l = 0; l < 12; l++) {
        int idx = tid + l * 256;
        int p = idx / CDIM, c = idx % CDIM;
        int hd = c / CH, cm = c % CH;
        const float* arow = &at[(hd * CH + cm) * CH];
        const float* vrow = &vs[p][hd * CH];
        float s = 0.f;
        #pragma unroll
        for (int e = 0; e < CH; e++) s += arow[e] * vrow[e];
        obase[(size_t)p * CDIM + c] = __float2bfloat16_rn(s);
    }
}

// ---------------- depthwise 3x3 on 510ch bf16 + GELU gate -> bf16 (stride 256) ----------------
__global__ void dwgate_kernel(const bf16* __restrict__ in, const float* __restrict__ kern,
                              bf16* __restrict__ out) {
    int idx = blockIdx.x * blockDim.x + threadIdx.x;
    if (idx >= (NPIX / 4) * HID) return;
    int c = idx % HID;
    int strip = idx / HID;
    int xs = (strip & 63) * 4;
    int y  = (strip >> 6) & 255;
    int b  = strip >> 14;

    float accA[4] = {0.f, 0.f, 0.f, 0.f};
    float accB[4] = {0.f, 0.f, 0.f, 0.f};

    #pragma unroll
    for (int dy = -1; dy <= 1; dy++) {
        int yy = y + dy;
        if (yy < 0 || yy > 255) continue;
        const bf16* rowp = in + ((size_t)((b << 8) + yy) << 8) * H2;
        float va[6], vb[6];
        #pragma unroll
        for (int j = 0; j < 6; j++) {
            int xx = xs - 1 + j;
            if (xx >= 0 && xx <= 255) {
                const bf16* pp = rowp + (size_t)xx * H2;
                va[j] = __bfloat162float(pp[c]);
                vb[j] = __bfloat162float(pp[c + HID]);
            } else {
                va[j] = 0.f; vb[j] = 0.f;
            }
        }
        #pragma unroll
        for (int dx = 0; dx < 3; dx++) {
            size_t koff = (size_t)((dy + 1) * 3 + dx) * H2;
            float ka = kern[koff + c];
            float kb = kern[koff + c + HID];
            #pragma unroll
            for (int ox = 0; ox < 4; ox++) {
                accA[ox] += va[ox + dx] * ka;
                accB[ox] += vb[ox + dx] * kb;
            }
        }
    }
    size_t pbase = (size_t)((b << 16) + (y << 8) + xs);
    #pragma unroll
    for (int ox = 0; ox < 4; ox++)
        out[(pbase + ox) * HIDP + c] = __float2bfloat16_rn(gelu_exact(accA[ox]) * accB[ox]);
    if (c == 0) {
        #pragma unroll
        for (int ox = 0; ox < 4; ox++) out[(pbase + ox) * HIDP + 255] = __float2bfloat16_rn(0.f);
    }
}

// ---------------- launcher ----------------
extern "C" void kernel_launch(void* const* d_in, const int* in_sizes, int n_in,
                              void* d_out, int out_size) {
    const float* x     = (const float*)d_in[0];
    const float* ln1g  = (const float*)d_in[1];
    const float* ln1b  = (const float*)d_in[2];
    const float* ln2g  = (const float*)d_in[3];
    const float* ln2b  = (const float*)d_in[4];
    const float* qkvw  = (const float*)d_in[5];
    const float* qkvdw = (const float*)d_in[6];
    const float* temp  = (const float*)d_in[7];
    const float* aow   = (const float*)d_in[8];
    const float* fiw   = (const float*)d_in[9];
    const float* fdw   = (const float*)d_in[10];
    const float* fow   = (const float*)d_in[11];
    float* out = (float*)d_out;

    bf16 *t0, *t1, *t2, *gt, *ybf, *wq, *wa, *wi, *wo;
    float *x2, *nrm, *att;
    cudaGetSymbolAddress((void**)&t0,  g_t0);
    cudaGetSymbolAddress((void**)&t1,  g_t1);
    cudaGetSymbolAddress((void**)&t2,  g_t2);
    cudaGetSymbolAddress((void**)&gt,  g_gt);
    cudaGetSymbolAddress((void**)&ybf, g_ybf);
    cudaGetSymbolAddress((void**)&x2,  g_x2);
    cudaGetSymbolAddress((void**)&nrm, g_nrm);
    cudaGetSymbolAddress((void**)&att, g_att);
    cudaGetSymbolAddress((void**)&wq,  g_wq);
    cudaGetSymbolAddress((void**)&wa,  g_wa);
    cudaGetSymbolAddress((void**)&wi,  g_wi);
    cudaGetSymbolAddress((void**)&wo,  g_wo);

    const int cvt_total = CDIM * QKV + CDIM * CDIM + CDIM * H2 + HID * CDIM;
    cvt_all_kernel<<<(cvt_total + 255) / 256, 256>>>(qkvw, aow, fiw, fow, wq, wa, wi, wo);
    init_kernel<<<1, 256>>>(nrm, att);

    // attention branch
    ln_kernel<<<2048, 256>>>(x, ln1g, ln1b, ybf);
    gemm_k<6, 96, 1, true><<<dim3(3, 1024), 256>>>(ybf, wq, nullptr, t0, CDIM, CDIM, QKV);
    dwconv288_kernel<<<(NPIX / 4) * 36 / 256, 256>>>(t0, qkvdw, t1);
    norms_kernel<<<dim3(64, 2), 192>>>(t1, nrm);
    qkt_kernel<<<dim3(32, 4), 256>>>(t1, att);
    softmax_kernel<<<4, 64>>>(att, nrm, temp);
    attnapply_kernel<<<dim3(2048, 2), 256>>>(t1, att, ybf);
    gemm_k<6, 96, 1, false><<<dim3(1, 1024), 256>>>(ybf, wa, x, x2, CDIM, CDIM, CDIM);

    // FFN branch
    ln_kernel<<<2048, 256>>>(x2, ln2g, ln2b, ybf);
    gemm_k<4, 96, 1, true><<<dim3(8, 1024), 256>>>(ybf, wi, nullptr, t2, CDIM, CDIM, H2);
    dwgate_kernel<<<((NPIX / 4) * HID + 255) / 256, 256>>>(t2, fdw, gt);
    gemm_k<6, 64, 4, false><<<dim3(1, 1024), 256>>>(gt, wo, x2, out, HIDP, HID, CDIM);
}